// round 16
// baseline (speedup 1.0000x reference)
#include <cuda_runtime.h>

#define NBLK   10
#define NBATCH 2048
#define NCH    64
#define NSKIP  96
#define TILE   16
#define NCOLS  1023
#define CURP   68
#define SSP    100
#define NBUF   ((size_t)NBATCH*NCH*NCOLS)   /* 134086656 */

typedef unsigned long long u64;

__device__ __forceinline__ u64 pk2(float a, float b) {
    u64 r; asm("mov.b64 %0, {%1, %2};" : "=l"(r) : "f"(a), "f"(b)); return r;
}
__device__ __forceinline__ u64 dup2(float a) {
    u64 r; asm("mov.b64 %0, {%1, %1};" : "=l"(r) : "f"(a)); return r;
}
__device__ __forceinline__ u64 fma2p(u64 a, u64 b, u64 c) {
    u64 d; asm("fma.rn.f32x2 %0, %1, %2, %3;" : "=l"(d) : "l"(a), "l"(b), "l"(c));
    return d;
}
__device__ __forceinline__ u64 add2p(u64 a, u64 b) {
    u64 d; asm("add.rn.f32x2 %0, %1, %2;" : "=l"(d) : "l"(a), "l"(b)); return d;
}
__device__ __forceinline__ void up2(u64 v, float& a, float& b) {
    asm("mov.b64 {%0, %1}, %2;" : "=f"(a), "=f"(b) : "l"(v));
}
__device__ __forceinline__ float tanh_ap(float x) {
    float y; asm("tanh.approx.f32 %0, %1;" : "=f"(y) : "f"(x)); return y;
}

#define BAR_TOP() asm volatile("bar.sync 1, 256;" ::: "memory")
#define BAR_MID() asm volatile("bar.sync 3, 256;" ::: "memory")
#define BAR_HEAD() asm volatile("bar.sync 2, 128;" ::: "memory")

// smem layout (floats):
//  cur 0..1088 | zs 1088..2176 | del[2] 2176..4352 | wb[2] 4352..45312
//  wst 45312..51456 | bia[2] 51456..52032 | ssm 52032..53632 | hsm 53632..55232
#define SM_CUR   (sm)
#define SM_ZS    (sm + 1088)
#define SM_DEL(p)(sm + 2176 + (p)*1088)
#define SM_WB(p) (sm + 4352 + (p)*20480)
#define SM_WST   (sm + 45312)
#define SM_BIA(p)(sm + 51456 + (p)*288)
#define SM_SSM   (sm + 52032)
#define SM_HSM   (sm + 53632)

// ---------------------------------------------------------------------------
// Compute: 128 CTAs x 256 threads. Warps 0-3 = math (identical R12 per-thread
// shape: 2 samples x 4 ch, FFMA2, MUFU). Warps 4-7 = producers: double-buffer
// weights/taps/biases for block i+1 while block i computes; stage wst[i] and
// the nbuf insertion-column snapshot inside block i's f/g window.
// ---------------------------------------------------------------------------
__global__ __launch_bounds__(256, 1) void wn_compute(
    const float* __restrict__ x,   const float* __restrict__ buf,
    const float* __restrict__ inp_w, const float* __restrict__ inp_b,
    const float* __restrict__ fw0, const float* __restrict__ fw1, const float* __restrict__ fb,
    const float* __restrict__ gw0, const float* __restrict__ gw1, const float* __restrict__ gb,
    const float* __restrict__ rw,  const float* __restrict__ rb,
    const float* __restrict__ sw,  const float* __restrict__ sb,
    const float* __restrict__ h1w, const float* __restrict__ h1b,
    const float* __restrict__ h2w, const float* __restrict__ h2b,
    float* __restrict__ out, float* __restrict__ nbuf)
{
    extern __shared__ float sm[];
    const int tid  = threadIdx.x;
    const int lane = tid & 31;
    const int bbase = blockIdx.x * TILE;
    const bool is_consumer = (tid < 128);

    float* cur = SM_CUR;
    float* zs  = SM_ZS;
    float* wst = SM_WST;
    float* ssm = SM_SSM;
    float* hsm = SM_HSM;

    // ---------------- consumer-only registers ----------------
    const int sp = tid >> 4, tg = tid & 15;
    const int s0 = sp*2, s1 = s0+1, t0 = tg*4, ts = tg*6;
    u64 sa0 = 0ull, sa1 = 0ull, sa2 = 0ull;
    u64 sb0 = 0ull, sb1 = 0ull, sb2 = 0ull;

    // ---------------- producer-only indices ----------------
    const int ptid = tid - 128;               // 0..127 for producers
    const int pw   = (tid >> 5) - 4;          // producer warp 0..3

    if (is_consumer) {
        // warp-local x staging: warp w loads rows 4w..4w+3 (32 floats each)
        int w = tid >> 5;
        int row = 4*w + (lane >> 3);
        int col = (lane & 7) * 4;
        *(float4*)(zs + row*32 + col) =
            *(const float4*)(x + (size_t)(bbase+row)*32 + col);
        __syncwarp();

        // input projection: cur = x @ inp_w.T + inp_b
        float a0[4], a1[4];
        #pragma unroll
        for (int j = 0; j < 4; ++j) { a0[j] = inp_b[t0+j]; a1[j] = a0[j]; }
        #pragma unroll 8
        for (int k = 0; k < 32; ++k) {
            float x0 = zs[s0*32+k], x1 = zs[s1*32+k];
            #pragma unroll
            for (int j = 0; j < 4; ++j) {
                float w2 = inp_w[(t0+j)*32 + k];
                a0[j] += x0*w2; a1[j] += x1*w2;
            }
        }
        #pragma unroll
        for (int j = 0; j < 4; ++j) {
            cur[s0*CURP + t0 + j] = a0[j];
            cur[s1*CURP + t0 + j] = a1[j];
        }
    } else {
        // initial staging: block 0 weights + biases + taps into buffer 0
        float* wb = SM_WB(0);
        const float* srcs[5] = { fw0, fw1, gw0, gw1, rw };
        #pragma unroll
        for (int mm = 0; mm < 5; ++mm) {
            const float* s = srcs[mm]; float* d = wb + mm*4096;
            #pragma unroll
            for (int th = 0; th < 2; ++th) {
                int t = th*32 + lane;
                #pragma unroll
                for (int kc = 0; kc < 4; ++kc) {
                    int k0 = pw*16 + kc*4;
                    float4 v = *(const float4*)(s + t*64 + k0);
                    d[(k0+0)*64+t] = v.x; d[(k0+1)*64+t] = v.y;
                    d[(k0+2)*64+t] = v.z; d[(k0+3)*64+t] = v.w;
                }
            }
        }
        float* bia = SM_BIA(0);
        if (ptid < 64) {
            bia[ptid]     = fb[ptid];
            bia[64+ptid]  = gb[ptid];
            bia[128+ptid] = rb[ptid];
        }
        if (ptid < 96) bia[192+ptid] = sb[ptid];
        float* del = SM_DEL(0);
        #pragma unroll
        for (int it = 0; it < 8; ++it) {
            int idx = it*128 + ptid;          // 1024 = 16*64
            int s = idx >> 6, c = idx & 63;
            del[s*CURP + c] = buf[((size_t)(bbase+s)*NCH + c)*NCOLS + 0];
        }
    }

    for (int i = 0; i < NBLK; ++i) {
        const int p = i & 1;
        BAR_TOP();   // buf[p] staged; cur (entering block i) stable

        if (is_consumer) {
            float* wb = SM_WB(p);
            float* w0 = wb, *w1 = wb+4096, *w2 = wb+8192, *w3 = wb+12288;
            float* bia = SM_BIA(p);
            const float* dle = SM_DEL(p);

            // ---- f/g GEMMs ----
            u64 f0a = pk2(bia[t0],   bia[t0+1]),   f0b = pk2(bia[t0+2],   bia[t0+3]);
            u64 f1a = f0a, f1b = f0b;
            u64 g0a = pk2(bia[64+t0],bia[64+t0+1]),g0b = pk2(bia[64+t0+2],bia[64+t0+3]);
            u64 g1a = g0a, g1b = g0b;
            #pragma unroll 4
            for (int k4 = 0; k4 < 64; k4 += 4) {
                float4 D0v = *(const float4*)(dle + s0*CURP + k4);
                float4 D1v = *(const float4*)(dle + s1*CURP + k4);
                float4 C0v = *(const float4*)(cur + s0*CURP + k4);
                float4 C1v = *(const float4*)(cur + s1*CURP + k4);
                const float d0s[4] = {D0v.x, D0v.y, D0v.z, D0v.w};
                const float d1s[4] = {D1v.x, D1v.y, D1v.z, D1v.w};
                const float c0s[4] = {C0v.x, C0v.y, C0v.z, C0v.w};
                const float c1s[4] = {C1v.x, C1v.y, C1v.z, C1v.w};
                #pragma unroll
                for (int kk = 0; kk < 4; ++kk) {
                    int k = k4 + kk;
                    u64 D0 = dup2(d0s[kk]), D1 = dup2(d1s[kk]);
                    u64 C0 = dup2(c0s[kk]), C1 = dup2(c1s[kk]);
                    ulonglong2 wa = *(const ulonglong2*)(w0 + k*64 + t0);
                    ulonglong2 wbv = *(const ulonglong2*)(w1 + k*64 + t0);
                    ulonglong2 wc = *(const ulonglong2*)(w2 + k*64 + t0);
                    ulonglong2 wd = *(const ulonglong2*)(w3 + k*64 + t0);
                    f0a = fma2p(D0, wa.x, f0a); f0b = fma2p(D0, wa.y, f0b);
                    f0a = fma2p(C0, wbv.x, f0a); f0b = fma2p(C0, wbv.y, f0b);
                    f1a = fma2p(D1, wa.x, f1a); f1b = fma2p(D1, wa.y, f1b);
                    f1a = fma2p(C1, wbv.x, f1a); f1b = fma2p(C1, wbv.y, f1b);
                    g0a = fma2p(D0, wc.x, g0a); g0b = fma2p(D0, wc.y, g0b);
                    g0a = fma2p(C0, wd.x, g0a); g0b = fma2p(C0, wd.y, g0b);
                    g1a = fma2p(D1, wc.x, g1a); g1b = fma2p(D1, wc.y, g1b);
                    g1a = fma2p(C1, wd.x, g1a); g1b = fma2p(C1, wd.y, g1b);
                }
            }
            float f0[4], f1[4], g0[4], g1[4];
            up2(f0a, f0[0], f0[1]); up2(f0b, f0[2], f0[3]);
            up2(f1a, f1[0], f1[1]); up2(f1b, f1[2], f1[3]);
            up2(g0a, g0[0], g0[1]); up2(g0b, g0[2], g0[3]);
            up2(g1a, g1[0], g1[1]); up2(g1b, g1[2], g1[3]);

            float z0[4], z1[4];
            #pragma unroll
            for (int j = 0; j < 4; ++j) {
                z0[j] = tanh_ap(f0[j]) * (0.5f + 0.5f*tanh_ap(0.5f*g0[j]));
                z1[j] = tanh_ap(f1[j]) * (0.5f + 0.5f*tanh_ap(0.5f*g1[j]));
            }
            *(float4*)(zs + s0*CURP + t0) = make_float4(z0[0],z0[1],z0[2],z0[3]);
            *(float4*)(zs + s1*CURP + t0) = make_float4(z1[0],z1[1],z1[2],z1[3]);
            __syncwarp();   // z exchange is intra-warp
        } else {
            // ---- stage wst[i] (single-buffered; consumers use it after MID)
            const float* s2 = sw + i*NSKIP*NCH;       // [96][64] -> wst[64][96]
            #pragma unroll
            for (int th = 0; th < 3; ++th) {
                int t = th*32 + lane;
                #pragma unroll
                for (int kc = 0; kc < 4; ++kc) {
                    int k0 = pw*16 + kc*4;
                    float4 v = *(const float4*)(s2 + t*64 + k0);
                    wst[(k0+0)*96+t] = v.x; wst[(k0+1)*96+t] = v.y;
                    wst[(k0+2)*96+t] = v.z; wst[(k0+3)*96+t] = v.w;
                }
            }
            // ---- snapshot current entering block i -> nbuf insertion col
            int jcol = (2 << i) - 2;
            #pragma unroll
            for (int it = 0; it < 8; ++it) {
                int idx = it*128 + ptid;
                int s = idx >> 6, c = idx & 63;
                nbuf[((size_t)(bbase+s)*NCH + c)*NCOLS + jcol] = cur[s*CURP + c];
            }
        }

        BAR_MID();   // wst[i] ready; consumers done reading wb? (no: f/g done)

        if (is_consumer) {
            float* wb = SM_WB(p);
            float* wrs = wb + 16384;
            float* bia = SM_BIA(p);

            // ---- res + skip GEMMs ----
            u64 r0a = pk2(bia[128+t0],   bia[128+t0+1]);
            u64 r0b = pk2(bia[128+t0+2], bia[128+t0+3]);
            u64 r1a = r0a, r1b = r0b;
            #pragma unroll 4
            for (int k4 = 0; k4 < 64; k4 += 4) {
                float4 Z0v = *(const float4*)(zs + s0*CURP + k4);
                float4 Z1v = *(const float4*)(zs + s1*CURP + k4);
                const float z0s[4] = {Z0v.x, Z0v.y, Z0v.z, Z0v.w};
                const float z1s[4] = {Z1v.x, Z1v.y, Z1v.z, Z1v.w};
                #pragma unroll
                for (int kk = 0; kk < 4; ++kk) {
                    int k = k4 + kk;
                    u64 Z0 = dup2(z0s[kk]), Z1 = dup2(z1s[kk]);
                    ulonglong2 wv = *(const ulonglong2*)(wrs + k*64 + t0);
                    r0a = fma2p(Z0, wv.x, r0a); r0b = fma2p(Z0, wv.y, r0b);
                    r1a = fma2p(Z1, wv.x, r1a); r1b = fma2p(Z1, wv.y, r1b);
                    const u64* wsk = (const u64*)(wst + k*96 + ts);
                    u64 wk0 = wsk[0], wk1 = wsk[1], wk2 = wsk[2];
                    sa0 = fma2p(Z0, wk0, sa0); sa1 = fma2p(Z0, wk1, sa1);
                    sa2 = fma2p(Z0, wk2, sa2);
                    sb0 = fma2p(Z1, wk0, sb0); sb1 = fma2p(Z1, wk1, sb1);
                    sb2 = fma2p(Z1, wk2, sb2);
                }
            }
            {
                const u64* bb = (const u64*)(bia + 192 + ts);
                u64 b0 = bb[0], b1 = bb[1], b2 = bb[2];
                sa0 = add2p(sa0, b0); sa1 = add2p(sa1, b1); sa2 = add2p(sa2, b2);
                sb0 = add2p(sb0, b0); sb1 = add2p(sb1, b1); sb2 = add2p(sb2, b2);
            }

            // ---- residual update ----
            float r0[4], r1[4];
            up2(r0a, r0[0], r0[1]); up2(r0b, r0[2], r0[3]);
            up2(r1a, r1[0], r1[1]); up2(r1b, r1[2], r1[3]);
            float4 c4 = *(float4*)(cur + s0*CURP + t0);
            c4.x += 0.3f*r0[0]; c4.y += 0.3f*r0[1];
            c4.z += 0.3f*r0[2]; c4.w += 0.3f*r0[3];
            *(float4*)(cur + s0*CURP + t0) = c4;
            float4 d4 = *(float4*)(cur + s1*CURP + t0);
            d4.x += 0.3f*r1[0]; d4.y += 0.3f*r1[1];
            d4.z += 0.3f*r1[2]; d4.w += 0.3f*r1[3];
            *(float4*)(cur + s1*CURP + t0) = d4;
            __syncwarp();
        } else {
            if (i < NBLK-1) {
                // ---- stage buffer (i+1)&1 for next block ----
                const int q = (i+1) & 1;
                const int ib = i + 1;
                float* wb = SM_WB(q);
                const float* srcs[5] = { fw0 + ib*4096, fw1 + ib*4096,
                                         gw0 + ib*4096, gw1 + ib*4096,
                                         rw + ib*4096 };
                #pragma unroll
                for (int mm = 0; mm < 5; ++mm) {
                    const float* s = srcs[mm]; float* d = wb + mm*4096;
                    #pragma unroll
                    for (int th = 0; th < 2; ++th) {
                        int t = th*32 + lane;
                        #pragma unroll
                        for (int kc = 0; kc < 4; ++kc) {
                            int k0 = pw*16 + kc*4;
                            float4 v = *(const float4*)(s + t*64 + k0);
                            d[(k0+0)*64+t] = v.x; d[(k0+1)*64+t] = v.y;
                            d[(k0+2)*64+t] = v.z; d[(k0+3)*64+t] = v.w;
                        }
                    }
                }
                float* bia = SM_BIA(q);
                if (ptid < 64) {
                    bia[ptid]     = fb[ib*64+ptid];
                    bia[64+ptid]  = gb[ib*64+ptid];
                    bia[128+ptid] = rb[ib*64+ptid];
                }
                if (ptid < 96) bia[192+ptid] = sb[ib*NSKIP+ptid];
                float* del = SM_DEL(q);
                int off = (1 << ib) - 1;
                #pragma unroll
                for (int it = 0; it < 8; ++it) {
                    int idx = it*128 + ptid;
                    int s = idx >> 6, c = idx & 63;
                    del[s*CURP + c] =
                        buf[((size_t)(bbase+s)*NCH + c)*NCOLS + off];
                }
            } else {
                // ---- stage h1T into wb[0] (free: block 9 uses buffer 1) ----
                float* h1T = SM_WB(0);
                for (int idx = ptid; idx < NSKIP*NSKIP; idx += 128) {
                    int k = idx / 96, t = idx - k*96;
                    h1T[idx] = h1w[t*96 + k];
                }
            }
        }
    }

    BAR_TOP();   // h1T staged; final cur/skip sums complete

    if (is_consumer) {
        // ---- head ----
        {
            float ssum0[6], ssum1[6];
            up2(sa0, ssum0[0], ssum0[1]); up2(sa1, ssum0[2], ssum0[3]);
            up2(sa2, ssum0[4], ssum0[5]);
            up2(sb0, ssum1[0], ssum1[1]); up2(sb1, ssum1[2], ssum1[3]);
            up2(sb2, ssum1[4], ssum1[5]);
            #pragma unroll
            for (int j = 0; j < 6; ++j) {
                ssm[s0*SSP + ts + j] = fmaxf(ssum0[j], 0.f);
                ssm[s1*SSP + ts + j] = fmaxf(ssum1[j], 0.f);
            }
        }
        __syncwarp();   // ssm exchange is intra-warp
        const float* h1T = SM_WB(0);
        {
            float a0[6], a1[6];
            #pragma unroll
            for (int j = 0; j < 6; ++j) { a0[j] = h1b[ts+j]; a1[j] = a0[j]; }
            #pragma unroll 4
            for (int k = 0; k < 96; ++k) {
                float u0 = ssm[s0*SSP+k], u1 = ssm[s1*SSP+k];
                const float* wk = h1T + k*96 + ts;
                #pragma unroll
                for (int j = 0; j < 6; ++j) {
                    float w = wk[j];
                    a0[j] += u0*w; a1[j] += u1*w;
                }
            }
            #pragma unroll
            for (int j = 0; j < 6; ++j) {
                hsm[s0*SSP + ts + j] = fmaxf(a0[j], 0.f);
                hsm[s1*SSP + ts + j] = fmaxf(a1[j], 0.f);
            }
        }
        BAR_HEAD();     // hsm is read cross-warp below
        if (tid < 32) {
            int s = tid >> 1, jj = tid & 1;
            float a = h2b[jj];
            #pragma unroll 4
            for (int k = 0; k < 96; ++k)
                a += hsm[s*SSP+k] * h2w[jj*96+k];
            out[(bbase+s)*2 + jj] = a;
        }
    }
}

// ---------------------------------------------------------------------------
// Shift: dst[n] = src[n+1], fully coalesced, skipping the 10 insertion
// columns per row. Grid 8184 x 256 covers NBUF exactly. (R12-proven)
// ---------------------------------------------------------------------------
__global__ __launch_bounds__(256) void wn_shift(const float* __restrict__ src,
                                                float* __restrict__ dst)
{
    const int warp = threadIdx.x >> 5;
    const unsigned lane = threadIdx.x & 31;
    const size_t base = (size_t)blockIdx.x*16384 + (size_t)warp*2048;
    const float4* s4 = (const float4*)(src + base);
    float4*       d4 = (float4*)(dst + base);

    float bnd = 0.f;
    if (lane == 31) {
        size_t g = base + 2048;
        bnd = src[g < NBUF ? g : NBUF - 1];
    }
    float4 A[16];
    #pragma unroll
    for (int r = 0; r < 16; ++r) A[r] = s4[r*32 + lane];

    int col = (int)((base + (size_t)lane*4) % NCOLS);

    #pragma unroll
    for (int r = 0; r < 16; ++r) {
        float nd = __shfl_down_sync(0xffffffffu, A[r].x, 1);
        float n0 = (r < 15) ? __shfl_sync(0xffffffffu, A[r+1].x, 0) : bnd;
        float nxt = (lane == 31) ? n0 : nd;
        float4 v = make_float4(A[r].y, A[r].z, A[r].w, nxt);

        int c0 = col, c1 = col+1, c2 = col+2, c3 = col+3;
        if (c1 >= NCOLS) c1 -= NCOLS;
        if (c2 >= NCOLS) c2 -= NCOLS;
        if (c3 >= NCOLS) c3 -= NCOLS;
        bool i0 = ((c0+2) & (c0+1)) == 0;
        bool i1 = ((c1+2) & (c1+1)) == 0;
        bool i2 = ((c2+2) & (c2+1)) == 0;
        bool i3 = ((c3+2) & (c3+1)) == 0;
        if (!(i0 | i1 | i2 | i3)) {
            d4[r*32 + lane] = v;
        } else {
            float* p = (float*)(d4 + r*32 + lane);
            if (!i0) p[0] = v.x;
            if (!i1) p[1] = v.y;
            if (!i2) p[2] = v.z;
            if (!i3) p[3] = v.w;
        }
        col += 128;
        if (col >= NCOLS) col -= NCOLS;
    }
}

extern "C" void kernel_launch(void* const* d_in, const int* in_sizes, int n_in,
                              void* d_out, int out_size)
{
    const float* x     = (const float*)d_in[0];
    const float* buf   = (const float*)d_in[1];
    const float* inp_w = (const float*)d_in[2];
    const float* inp_b = (const float*)d_in[3];
    const float* fw0   = (const float*)d_in[4];
    const float* fw1   = (const float*)d_in[5];
    const float* fb    = (const float*)d_in[6];
    const float* gw0   = (const float*)d_in[7];
    const float* gw1   = (const float*)d_in[8];
    const float* gb    = (const float*)d_in[9];
    const float* rw    = (const float*)d_in[10];
    const float* rb    = (const float*)d_in[11];
    const float* sw    = (const float*)d_in[12];
    const float* sb    = (const float*)d_in[13];
    const float* h1w   = (const float*)d_in[14];
    const float* h1b   = (const float*)d_in[15];
    const float* h2w   = (const float*)d_in[16];
    const float* h2b   = (const float*)d_in[17];

    float* out  = (float*)d_out;            // (2048, 2)
    float* nbuf = out + NBATCH*2;           // (2048, 64, 1023)

    static cudaStream_t s2 = nullptr;
    static cudaEvent_t ev_fork = nullptr, ev_join = nullptr;
    if (!s2) {
        int lo, hi;
        cudaDeviceGetStreamPriorityRange(&lo, &hi);
        cudaStreamCreateWithPriority(&s2, cudaStreamNonBlocking, lo);
        cudaEventCreateWithFlags(&ev_fork, cudaEventDisableTiming);
        cudaEventCreateWithFlags(&ev_join, cudaEventDisableTiming);
    }

    const int smem_bytes = 55232 * (int)sizeof(float);   // 220,928 B
    cudaFuncSetAttribute(wn_compute, cudaFuncAttributeMaxDynamicSharedMemorySize,
                         smem_bytes);

    cudaEventRecord(ev_fork, 0);
    cudaStreamWaitEvent(s2, ev_fork, 0);

    wn_compute<<<NBATCH/TILE, 256, smem_bytes>>>(
        x, buf, inp_w, inp_b, fw0, fw1, fb, gw0, gw1, gb,
        rw, rb, sw, sb, h1w, h1b, h2w, h2b, out, nbuf);

    wn_shift<<<8184, 256, 0, s2>>>(buf, nbuf);
    cudaEventRecord(ev_join, s2);

    cudaStreamWaitEvent(0, ev_join, 0);
}

// round 17
// speedup vs baseline: 1.2525x; 1.2525x over previous
#include <cuda_runtime.h>

#define NBLK   10
#define NBATCH 2048
#define NCH    64
#define NSKIP  96
#define TILE   16
#define NCOLS  1023
#define CURP   68                      /* padded row stride for cur/del/z */
#define SSP    100                     /* padded row stride for skip/h */
#define NBUF   ((size_t)NBATCH*NCH*NCOLS)   /* 134086656 */

typedef unsigned long long u64;

__device__ __forceinline__ u64 pk2(float a, float b) {
    u64 r; asm("mov.b64 %0, {%1, %2};" : "=l"(r) : "f"(a), "f"(b)); return r;
}
__device__ __forceinline__ u64 dup2(float a) {
    u64 r; asm("mov.b64 %0, {%1, %1};" : "=l"(r) : "f"(a)); return r;
}
__device__ __forceinline__ u64 fma2p(u64 a, u64 b, u64 c) {
    u64 d; asm("fma.rn.f32x2 %0, %1, %2, %3;" : "=l"(d) : "l"(a), "l"(b), "l"(c));
    return d;
}
__device__ __forceinline__ u64 add2p(u64 a, u64 b) {
    u64 d; asm("add.rn.f32x2 %0, %1, %2;" : "=l"(d) : "l"(a), "l"(b)); return d;
}
__device__ __forceinline__ void up2(u64 v, float& a, float& b) {
    asm("mov.b64 {%0, %1}, %2;" : "=f"(a), "=f"(b) : "l"(v));
}
__device__ __forceinline__ float tanh_ap(float x) {
    float y; asm("tanh.approx.f32 %0, %1;" : "=f"(y) : "f"(x)); return y;
}

// ---------------------------------------------------------------------------
// Compute kernel (exact R12 champion): 128 CTAs x 128 threads, packed f32x2
// FMAs, float4 activation loads, MUFU tanh. Snapshots written directly to
// nbuf insertion columns.
// ---------------------------------------------------------------------------
__global__ __launch_bounds__(128, 1) void wn_compute(
    const float* __restrict__ x,   const float* __restrict__ buf,
    const float* __restrict__ inp_w, const float* __restrict__ inp_b,
    const float* __restrict__ fw0, const float* __restrict__ fw1, const float* __restrict__ fb,
    const float* __restrict__ gw0, const float* __restrict__ gw1, const float* __restrict__ gb,
    const float* __restrict__ rw,  const float* __restrict__ rb,
    const float* __restrict__ sw,  const float* __restrict__ sb,
    const float* __restrict__ h1w, const float* __restrict__ h1b,
    const float* __restrict__ h2w, const float* __restrict__ h2b,
    float* __restrict__ out, float* __restrict__ nbuf)
{
    extern __shared__ float sm[];
    float* cur = sm;                          // 16*68
    float* del = cur + TILE*CURP;             // 10*16*68
    float* zs  = del + NBLK*TILE*CURP;        // 16*68
    float* w0  = zs  + TILE*CURP;             // 4096  (transposed [k][t], row 64)
    float* w1  = w0 + 4096;
    float* w2  = w1 + 4096;
    float* w3  = w2 + 4096;
    float* wrs = w3 + 4096;                   // res weights
    float* wst = wrs + 4096;                  // 64*96 skip weights transposed
    float* bia = wst + 6144;                  // fb[64] gb[64] rb[64] sb[96]
    float* ssm = bia + 288;                   // 16*100 skip sums
    float* hsm = ssm + TILE*SSP;              // 16*100 hidden

    const int tid  = threadIdx.x;
    const int lane = tid & 31, warp = tid >> 5;
    const int sp = tid >> 4, tg = tid & 15;
    const int s0 = sp*2, s1 = s0+1, t0 = tg*4;
    const int bbase = blockIdx.x * TILE;

    for (int idx = tid; idx < TILE*32; idx += 128) {
        int s = idx >> 5, k = idx & 31;
        zs[idx] = x[(bbase+s)*32 + k];
    }
    __syncthreads();

    {
        float a0[4], a1[4];
        #pragma unroll
        for (int j = 0; j < 4; ++j) { a0[j] = inp_b[t0+j]; a1[j] = a0[j]; }
        #pragma unroll 8
        for (int k = 0; k < 32; ++k) {
            float x0 = zs[s0*32+k], x1 = zs[s1*32+k];
            #pragma unroll
            for (int j = 0; j < 4; ++j) {
                float w = inp_w[(t0+j)*32 + k];
                a0[j] += x0*w; a1[j] += x1*w;
            }
        }
        #pragma unroll
        for (int j = 0; j < 4; ++j) {
            cur[s0*CURP + t0 + j] = a0[j];
            cur[s1*CURP + t0 + j] = a1[j];
        }
    }

    for (int idx = tid; idx < NBLK*TILE*NCH; idx += 128) {
        int i = idx >> 10;
        int r = idx & 1023;
        int s = r >> 6, c = r & 63;
        int off = (1 << i) - 1;
        del[(i*TILE + s)*CURP + c] =
            buf[((size_t)(bbase+s)*NCH + c)*NCOLS + off];
    }

    u64 sa0 = 0ull, sa1 = 0ull, sa2 = 0ull;
    u64 sb0 = 0ull, sb1 = 0ull, sb2 = 0ull;
    const int ts = tg*6;

    for (int i = 0; i < NBLK; ++i) {
        __syncthreads();

        {
            int jcol = (2 << i) - 2;                  // 2^(i+1)-2
            for (int idx = tid; idx < TILE*NCH; idx += 128) {
                int s = idx >> 6, c = idx & 63;
                nbuf[((size_t)(bbase+s)*NCH + c)*NCOLS + jcol] = cur[s*CURP + c];
            }
        }

        {
            const float* srcs[5] = { fw0 + i*4096, fw1 + i*4096, gw0 + i*4096,
                                     gw1 + i*4096, rw + i*4096 };
            float* dsts[5] = { w0, w1, w2, w3, wrs };
            #pragma unroll
            for (int mm = 0; mm < 5; ++mm) {
                const float* s = srcs[mm]; float* d = dsts[mm];
                #pragma unroll
                for (int th = 0; th < 2; ++th) {
                    int t = th*32 + lane;
                    #pragma unroll
                    for (int kc = 0; kc < 4; ++kc) {
                        int k0 = warp*16 + kc*4;
                        float4 v = *(const float4*)(s + t*64 + k0);
                        d[(k0+0)*64+t] = v.x; d[(k0+1)*64+t] = v.y;
                        d[(k0+2)*64+t] = v.z; d[(k0+3)*64+t] = v.w;
                    }
                }
            }
            const float* s = sw + i*NSKIP*NCH;   // [96][64] -> wst[64][96]
            #pragma unroll
            for (int th = 0; th < 3; ++th) {
                int t = th*32 + lane;
                #pragma unroll
                for (int kc = 0; kc < 4; ++kc) {
                    int k0 = warp*16 + kc*4;
                    float4 v = *(const float4*)(s + t*64 + k0);
                    wst[(k0+0)*96+t] = v.x; wst[(k0+1)*96+t] = v.y;
                    wst[(k0+2)*96+t] = v.z; wst[(k0+3)*96+t] = v.w;
                }
            }
            if (tid < 64) {
                bia[tid]      = fb[i*64+tid];
                bia[64+tid]   = gb[i*64+tid];
                bia[128+tid]  = rb[i*64+tid];
            }
            if (tid < 96) bia[192+tid] = sb[i*NSKIP+tid];
        }
        __syncthreads();

        u64 f0a = pk2(bia[t0],   bia[t0+1]),   f0b = pk2(bia[t0+2],   bia[t0+3]);
        u64 f1a = f0a, f1b = f0b;
        u64 g0a = pk2(bia[64+t0],bia[64+t0+1]),g0b = pk2(bia[64+t0+2],bia[64+t0+3]);
        u64 g1a = g0a, g1b = g0b;
        const float* dle = del + i*TILE*CURP;
        #pragma unroll 4
        for (int k4 = 0; k4 < 64; k4 += 4) {
            float4 D0v = *(const float4*)(dle + s0*CURP + k4);
            float4 D1v = *(const float4*)(dle + s1*CURP + k4);
            float4 C0v = *(const float4*)(cur + s0*CURP + k4);
            float4 C1v = *(const float4*)(cur + s1*CURP + k4);
            const float d0s[4] = {D0v.x, D0v.y, D0v.z, D0v.w};
            const float d1s[4] = {D1v.x, D1v.y, D1v.z, D1v.w};
            const float c0s[4] = {C0v.x, C0v.y, C0v.z, C0v.w};
            const float c1s[4] = {C1v.x, C1v.y, C1v.z, C1v.w};
            #pragma unroll
            for (int kk = 0; kk < 4; ++kk) {
                int k = k4 + kk;
                u64 D0 = dup2(d0s[kk]), D1 = dup2(d1s[kk]);
                u64 C0 = dup2(c0s[kk]), C1 = dup2(c1s[kk]);
                ulonglong2 wa = *(const ulonglong2*)(w0 + k*64 + t0);
                ulonglong2 wb = *(const ulonglong2*)(w1 + k*64 + t0);
                ulonglong2 wc = *(const ulonglong2*)(w2 + k*64 + t0);
                ulonglong2 wd = *(const ulonglong2*)(w3 + k*64 + t0);
                f0a = fma2p(D0, wa.x, f0a); f0b = fma2p(D0, wa.y, f0b);
                f0a = fma2p(C0, wb.x, f0a); f0b = fma2p(C0, wb.y, f0b);
                f1a = fma2p(D1, wa.x, f1a); f1b = fma2p(D1, wa.y, f1b);
                f1a = fma2p(C1, wb.x, f1a); f1b = fma2p(C1, wb.y, f1b);
                g0a = fma2p(D0, wc.x, g0a); g0b = fma2p(D0, wc.y, g0b);
                g0a = fma2p(C0, wd.x, g0a); g0b = fma2p(C0, wd.y, g0b);
                g1a = fma2p(D1, wc.x, g1a); g1b = fma2p(D1, wc.y, g1b);
                g1a = fma2p(C1, wd.x, g1a); g1b = fma2p(C1, wd.y, g1b);
            }
        }
        float f0[4], f1[4], g0[4], g1[4];
        up2(f0a, f0[0], f0[1]); up2(f0b, f0[2], f0[3]);
        up2(f1a, f1[0], f1[1]); up2(f1b, f1[2], f1[3]);
        up2(g0a, g0[0], g0[1]); up2(g0b, g0[2], g0[3]);
        up2(g1a, g1[0], g1[1]); up2(g1b, g1[2], g1[3]);

        float z0[4], z1[4];
        #pragma unroll
        for (int j = 0; j < 4; ++j) {
            z0[j] = tanh_ap(f0[j]) * (0.5f + 0.5f*tanh_ap(0.5f*g0[j]));
            z1[j] = tanh_ap(f1[j]) * (0.5f + 0.5f*tanh_ap(0.5f*g1[j]));
        }
        *(float4*)(zs + s0*CURP + t0) = make_float4(z0[0],z0[1],z0[2],z0[3]);
        *(float4*)(zs + s1*CURP + t0) = make_float4(z1[0],z1[1],z1[2],z1[3]);
        __syncthreads();

        u64 r0a = pk2(bia[128+t0],   bia[128+t0+1]);
        u64 r0b = pk2(bia[128+t0+2], bia[128+t0+3]);
        u64 r1a = r0a, r1b = r0b;
        #pragma unroll 4
        for (int k4 = 0; k4 < 64; k4 += 4) {
            float4 Z0v = *(const float4*)(zs + s0*CURP + k4);
            float4 Z1v = *(const float4*)(zs + s1*CURP + k4);
            const float z0s[4] = {Z0v.x, Z0v.y, Z0v.z, Z0v.w};
            const float z1s[4] = {Z1v.x, Z1v.y, Z1v.z, Z1v.w};
            #pragma unroll
            for (int kk = 0; kk < 4; ++kk) {
                int k = k4 + kk;
                u64 Z0 = dup2(z0s[kk]), Z1 = dup2(z1s[kk]);
                ulonglong2 wv = *(const ulonglong2*)(wrs + k*64 + t0);
                r0a = fma2p(Z0, wv.x, r0a); r0b = fma2p(Z0, wv.y, r0b);
                r1a = fma2p(Z1, wv.x, r1a); r1b = fma2p(Z1, wv.y, r1b);
                const u64* wsk = (const u64*)(wst + k*96 + ts);
                u64 wk0 = wsk[0], wk1 = wsk[1], wk2 = wsk[2];
                sa0 = fma2p(Z0, wk0, sa0); sa1 = fma2p(Z0, wk1, sa1);
                sa2 = fma2p(Z0, wk2, sa2);
                sb0 = fma2p(Z1, wk0, sb0); sb1 = fma2p(Z1, wk1, sb1);
                sb2 = fma2p(Z1, wk2, sb2);
            }
        }
        {
            const u64* bb = (const u64*)(bia + 192 + ts);
            u64 b0 = bb[0], b1 = bb[1], b2 = bb[2];
            sa0 = add2p(sa0, b0); sa1 = add2p(sa1, b1); sa2 = add2p(sa2, b2);
            sb0 = add2p(sb0, b0); sb1 = add2p(sb1, b1); sb2 = add2p(sb2, b2);
        }

        {
            float r0[4], r1[4];
            up2(r0a, r0[0], r0[1]); up2(r0b, r0[2], r0[3]);
            up2(r1a, r1[0], r1[1]); up2(r1b, r1[2], r1[3]);
            float4 c4 = *(float4*)(cur + s0*CURP + t0);
            c4.x += 0.3f*r0[0]; c4.y += 0.3f*r0[1];
            c4.z += 0.3f*r0[2]; c4.w += 0.3f*r0[3];
            *(float4*)(cur + s0*CURP + t0) = c4;
            float4 d4 = *(float4*)(cur + s1*CURP + t0);
            d4.x += 0.3f*r1[0]; d4.y += 0.3f*r1[1];
            d4.z += 0.3f*r1[2]; d4.w += 0.3f*r1[3];
            *(float4*)(cur + s1*CURP + t0) = d4;
        }
    }

    __syncthreads();
    {
        float ssum0[6], ssum1[6];
        up2(sa0, ssum0[0], ssum0[1]); up2(sa1, ssum0[2], ssum0[3]);
        up2(sa2, ssum0[4], ssum0[5]);
        up2(sb0, ssum1[0], ssum1[1]); up2(sb1, ssum1[2], ssum1[3]);
        up2(sb2, ssum1[4], ssum1[5]);
        #pragma unroll
        for (int j = 0; j < 6; ++j) {
            ssm[s0*SSP + ts + j] = fmaxf(ssum0[j], 0.f);
            ssm[s1*SSP + ts + j] = fmaxf(ssum1[j], 0.f);
        }
    }
    float* h1T = w0;
    for (int idx = tid; idx < NSKIP*NSKIP; idx += 128) {
        int k = idx / 96, t = idx - k*96;
        h1T[idx] = h1w[t*96 + k];
    }
    __syncthreads();
    {
        float a0[6], a1[6];
        #pragma unroll
        for (int j = 0; j < 6; ++j) { a0[j] = h1b[ts+j]; a1[j] = a0[j]; }
        #pragma unroll 4
        for (int k = 0; k < 96; ++k) {
            float u0 = ssm[s0*SSP+k], u1 = ssm[s1*SSP+k];
            const float* wk = h1T + k*96 + ts;
            #pragma unroll
            for (int j = 0; j < 6; ++j) {
                float w = wk[j];
                a0[j] += u0*w; a1[j] += u1*w;
            }
        }
        #pragma unroll
        for (int j = 0; j < 6; ++j) {
            hsm[s0*SSP + ts + j] = fmaxf(a0[j], 0.f);
            hsm[s1*SSP + ts + j] = fmaxf(a1[j], 0.f);
        }
    }
    __syncthreads();
    if (tid < 32) {
        int s = tid >> 1, jj = tid & 1;
        float a = h2b[jj];
        #pragma unroll 4
        for (int k = 0; k < 96; ++k)
            a += hsm[s*SSP+k] * h2w[jj*96+k];
        out[(bbase+s)*2 + jj] = a;
    }
}

// ---------------------------------------------------------------------------
// Shift: dst[n] = src[n+1], fully coalesced, skipping insertion columns.
// SMALLER per-thread footprint: 8 x float4 (~52 regs) so TWO shift CTAs
// co-reside with a compute CTA (2x co-resident warps during overlap).
// Warp owns 1024 contiguous floats; grid 16368 x 256 covers NBUF exactly.
// ---------------------------------------------------------------------------
__global__ __launch_bounds__(256) void wn_shift(const float* __restrict__ src,
                                                float* __restrict__ dst)
{
    const int warp = threadIdx.x >> 5;
    const unsigned lane = threadIdx.x & 31;
    const size_t base = (size_t)blockIdx.x*8192 + (size_t)warp*1024;  // floats
    const float4* s4 = (const float4*)(src + base);
    float4*       d4 = (float4*)(dst + base);

    float bnd = 0.f;
    if (lane == 31) {
        size_t g = base + 1024;
        bnd = src[g < NBUF ? g : NBUF - 1];   // clamp slot is an insertion col
    }
    float4 A[8];
    #pragma unroll
    for (int r = 0; r < 8; ++r) A[r] = s4[r*32 + lane];

    int col = (int)((base + (size_t)lane*4) % NCOLS);   // col of element 0, r=0

    #pragma unroll
    for (int r = 0; r < 8; ++r) {
        float nd = __shfl_down_sync(0xffffffffu, A[r].x, 1);
        float n0 = (r < 7) ? __shfl_sync(0xffffffffu, A[r+1].x, 0) : bnd;
        float nxt = (lane == 31) ? n0 : nd;
        float4 v = make_float4(A[r].y, A[r].z, A[r].w, nxt);

        int c0 = col, c1 = col+1, c2 = col+2, c3 = col+3;
        if (c1 >= NCOLS) c1 -= NCOLS;
        if (c2 >= NCOLS) c2 -= NCOLS;
        if (c3 >= NCOLS) c3 -= NCOLS;
        bool i0 = ((c0+2) & (c0+1)) == 0;
        bool i1 = ((c1+2) & (c1+1)) == 0;
        bool i2 = ((c2+2) & (c2+1)) == 0;
        bool i3 = ((c3+2) & (c3+1)) == 0;
        if (!(i0 | i1 | i2 | i3)) {
            d4[r*32 + lane] = v;
        } else {
            float* p = (float*)(d4 + r*32 + lane);
            if (!i0) p[0] = v.x;
            if (!i1) p[1] = v.y;
            if (!i2) p[2] = v.z;
            if (!i3) p[3] = v.w;
        }
        col += 128;
        if (col >= NCOLS) col -= NCOLS;
    }
}

extern "C" void kernel_launch(void* const* d_in, const int* in_sizes, int n_in,
                              void* d_out, int out_size)
{
    const float* x     = (const float*)d_in[0];
    const float* buf   = (const float*)d_in[1];
    const float* inp_w = (const float*)d_in[2];
    const float* inp_b = (const float*)d_in[3];
    const float* fw0   = (const float*)d_in[4];
    const float* fw1   = (const float*)d_in[5];
    const float* fb    = (const float*)d_in[6];
    const float* gw0   = (const float*)d_in[7];
    const float* gw1   = (const float*)d_in[8];
    const float* gb    = (const float*)d_in[9];
    const float* rw    = (const float*)d_in[10];
    const float* rb    = (const float*)d_in[11];
    const float* sw    = (const float*)d_in[12];
    const float* sb    = (const float*)d_in[13];
    const float* h1w   = (const float*)d_in[14];
    const float* h1b   = (const float*)d_in[15];
    const float* h2w   = (const float*)d_in[16];
    const float* h2b   = (const float*)d_in[17];

    float* out  = (float*)d_out;            // (2048, 2)
    float* nbuf = out + NBATCH*2;           // (2048, 64, 1023)

    // lazy one-time creation (first call = correctness run, before capture)
    static cudaStream_t s2 = nullptr;
    static cudaEvent_t ev_fork = nullptr, ev_join = nullptr;
    if (!s2) {
        int lo, hi;
        cudaDeviceGetStreamPriorityRange(&lo, &hi);   // lo = LEAST priority
        cudaStreamCreateWithPriority(&s2, cudaStreamNonBlocking, lo);
        cudaEventCreateWithFlags(&ev_fork, cudaEventDisableTiming);
        cudaEventCreateWithFlags(&ev_join, cudaEventDisableTiming);
    }

    const int smem_bytes = (TILE*CURP*(NBLK+2) + 5*4096 + 6144 + 288 + 2*TILE*SSP)
                           * (int)sizeof(float);     // 172672 B
    cudaFuncSetAttribute(wn_compute, cudaFuncAttributeMaxDynamicSharedMemorySize,
                         smem_bytes);

    // fork: compute launched FIRST (grabs its SM slots); shift fills the rest
    cudaEventRecord(ev_fork, 0);
    cudaStreamWaitEvent(s2, ev_fork, 0);

    wn_compute<<<NBATCH/TILE, 128, smem_bytes>>>(
        x, buf, inp_w, inp_b, fw0, fw1, fb, gw0, gw1, gb,
        rw, rb, sw, sb, h1w, h1b, h2w, h2b, out, nbuf);

    wn_shift<<<16368, 256, 0, s2>>>(buf, nbuf);
    cudaEventRecord(ev_join, s2);

    // join: main stream waits for shift so the graph completes both branches
    cudaStreamWaitEvent(0, ev_join, 0);
}